// round 13
// baseline (speedup 1.0000x reference)
#include <cuda_runtime.h>
#include <cuda_bf16.h>
#include <cstdint>
#include <cstddef>

#define TSEQ 912
#define NB   512
#define HID  128
#define G4   512   // 4*H

typedef unsigned long long ull;

// ---------------- device scratch (static, allowed) ----------------
// layout: [t][bgrp (NB/4)][gate (512)][4 batch]
__device__ float g_xg[(size_t)TSEQ * (NB / 4) * G4 * 4];
__device__ float g_bufA[(size_t)NB * TSEQ * HID];   // [b][t][u]
__device__ float g_bufB[(size_t)NB * TSEQ * HID];
__device__ float g_hN[4 * NB * HID];                // [layer][b][u]

// ---------------- f32x2 helpers (layer-0 precompute) ----------------
__device__ __forceinline__ ull pack2(float lo, float hi) {
    ull r;
    asm("mov.b64 %0, {%1, %2};" : "=l"(r)
        : "r"(__float_as_uint(lo)), "r"(__float_as_uint(hi)));
    return r;
}
__device__ __forceinline__ float2 unpack2(ull v) {
    unsigned lo, hi;
    asm("mov.b64 {%0, %1}, %2;" : "=r"(lo), "=r"(hi) : "l"(v));
    return make_float2(__uint_as_float(lo), __uint_as_float(hi));
}
__device__ __forceinline__ void fma2(ull& d, ull a, ull b) {
    asm("fma.rn.f32x2 %0, %1, %2, %0;" : "+l"(d) : "l"(a), "l"(b));
}

// ---------------- activations ----------------
__device__ __forceinline__ float sigx(float x) {
    x = fminf(fmaxf(x, -30.f), 30.f);
    return __fdividef(1.f, 1.f + __expf(-x));
}
__device__ __forceinline__ float tanhx(float x) {
    x = fminf(fmaxf(x, -15.f), 15.f);
    float e = __expf(2.f * x);
    return __fdividef(e - 1.f, e + 1.f);
}

// ---------------- bf16 helpers ----------------
__device__ __forceinline__ float bf16_rn(float x) {
    return __bfloat162float(__float2bfloat16(x));
}
__device__ __forceinline__ uint32_t pack_bf16x2(float a, float b) {
    uint32_t r;
    asm("cvt.rn.bf16x2.f32 %0, %1, %2;" : "=r"(r) : "f"(b), "f"(a));
    return r;
}

// ---------------- cp.async helpers (layer-0 precompute) ----------------
__device__ __forceinline__ unsigned smem_u32(const void* p) {
    return (unsigned)__cvta_generic_to_shared(p);
}
__device__ __forceinline__ void cpasync16(unsigned saddr, const void* gaddr) {
    asm volatile("cp.async.ca.shared.global [%0], [%1], 16;"
                 :: "r"(saddr), "l"(gaddr));
}
__device__ __forceinline__ void cpasync_commit() {
    asm volatile("cp.async.commit_group;");
}
__device__ __forceinline__ void cpasync_wait0() {
    asm volatile("cp.async.wait_group 0;");
}

// ---------------- warp mma m16n8k16 bf16 ----------------
__device__ __forceinline__ void mma16816(float* d, const uint32_t* a,
                                         const uint32_t* b) {
    asm volatile(
        "mma.sync.aligned.m16n8k16.row.col.f32.bf16.bf16.f32 "
        "{%0,%1,%2,%3}, {%4,%5,%6,%7}, {%8,%9}, {%0,%1,%2,%3};"
        : "+f"(d[0]), "+f"(d[1]), "+f"(d[2]), "+f"(d[3])
        : "r"(a[0]), "r"(a[1]), "r"(a[2]), "r"(a[3]), "r"(b[0]), "r"(b[1]));
}

// shared layouts:
// recurrent: full alo (128 KB) + 2x512-word B stage
#define REC_BST_OFF  131072
#define REC_SMEM     (131072 + 4096)         // 135168
// precompute: full alo (128 KB) + 2 buf x 4 frag x 512-word B stage
#define PRE_BST_OFF  131072
#define PRE_SMEM     (131072 + 16384)        // 147456

// ---- precompute weight conversion (2 tiles per warp, 512 threads) ----
__device__ __forceinline__ void convert_weights_pre(
    const float* __restrict__ W, char* alo, int w, int gid, int qid, int l,
    uint32_t wa[2][8][4])
{
#pragma unroll
    for (int mt = 0; mt < 2; mt++) {
#pragma unroll
        for (int kt = 0; kt < 8; kt++) {
            uint32_t lo4[4];
#pragma unroll
            for (int q = 0; q < 4; q++) {
                int rf = gid + (q & 1) * 8;
                int row = w * 32 + mt * 16 + rf;
                int col = kt * 16 + qid * 2 + (q >> 1) * 8;
                float w0 = W[row * 128 + col];
                float w1 = W[row * 128 + col + 1];
                float h0 = bf16_rn(w0), h1 = bf16_rn(w1);
                wa[mt][kt][q] = pack_bf16x2(h0, h1);
                lo4[q] = pack_bf16x2(w0 - h0, w1 - h1);
            }
            *(uint4*)(alo + (((w * 2 + mt) * 8 + kt) * 32 + l) * 16) =
                make_uint4(lo4[0], lo4[1], lo4[2], lo4[3]);
        }
    }
}

// ---- recurrent weight conversion: ONE tile per warp-team (1024 thr) ----
// tile t (0..31): row rf -> gate (rf>>2)*128 + tile*4 + (rf&3)
__device__ __forceinline__ void convert_weights_rec(
    const float* __restrict__ W, char* alo, int tile, int gid, int qid, int l,
    uint32_t wa[8][4])
{
#pragma unroll
    for (int kt = 0; kt < 8; kt++) {
        uint32_t lo4[4];
#pragma unroll
        for (int q = 0; q < 4; q++) {
            int rf = gid + (q & 1) * 8;
            int row = (rf >> 2) * 128 + tile * 4 + (rf & 3);
            int col = kt * 16 + qid * 2 + (q >> 1) * 8;
            float w0 = W[row * 128 + col];
            float w1 = W[row * 128 + col + 1];
            float h0 = bf16_rn(w0), h1 = bf16_rn(w1);
            wa[kt][q] = pack_bf16x2(h0, h1);
            lo4[q] = pack_bf16x2(w0 - h0, w1 - h1);
        }
        *(uint4*)(alo + ((tile * 8 + kt) * 32 + l) * 16) =
            make_uint4(lo4[0], lo4[1], lo4[2], lo4[3]);
    }
}

// =====================================================================
// Layer-0 precompute (K=32, fp32 FFMA path)
// =====================================================================
template<int K>
__global__ __launch_bounds__(512, 1)
void precompute_kernel(const float* __restrict__ xext,
                       const float* __restrict__ Wih,
                       const float* __restrict__ bih,
                       const float* __restrict__ bhh)
{
    extern __shared__ float sm[];
    constexpr int CHUNKS = 8 * K / 4;
    float* xt = sm;                              // [2][8][K]

    const int j = threadIdx.x;
    const float* in = xext;

    ull wregp[K / 2];
#pragma unroll
    for (int kk = 0; kk < K / 2; kk++)
        wregp[kk] = pack2(Wih[j * K + 2 * kk], Wih[j * K + 2 * kk + 1]);
    const float bsum = bih[j] + bhh[j];

    const unsigned xt_s = smem_u32(xt);
    const int NT = TSEQ * (NB / 8);
    const int stride = gridDim.x;

    int tile0 = blockIdx.x;
    if (tile0 < NT && j < CHUNKS) {
        int t  = tile0 >> 6;
        int b0 = (tile0 & 63) << 3;
        int r  = j / (K / 4), kk = j % (K / 4);
        cpasync16(xt_s + (unsigned)(r * K + kk * 4) * 4,
                  &in[((size_t)(b0 + r) * TSEQ + t) * K + kk * 4]);
    }
    cpasync_commit();

    int buf = 0;
    for (int tile = blockIdx.x; tile < NT; tile += stride) {
        cpasync_wait0();
        __syncthreads();

        int nxt = tile + stride;
        if (nxt < NT && j < CHUNKS) {
            int tn  = nxt >> 6;
            int bn0 = (nxt & 63) << 3;
            int r   = j / (K / 4), kk = j % (K / 4);
            cpasync16(xt_s + (unsigned)((buf ^ 1) * 8 * K + r * K + kk * 4) * 4,
                      &in[((size_t)(bn0 + r) * TSEQ + tn) * K + kk * 4]);
        }
        cpasync_commit();

        const float* xtb = xt + buf * 8 * K;
        const int t  = tile >> 6;
        const int b0 = (tile & 63) << 3;

        ull acc[8] = {0, 0, 0, 0, 0, 0, 0, 0};
#pragma unroll
        for (int kq = 0; kq < K / 4; kq++) {
            ull w0 = wregp[2 * kq], w1 = wregp[2 * kq + 1];
#pragma unroll
            for (int r = 0; r < 8; r++) {
                ulonglong2 xv = *(const ulonglong2*)&xtb[r * K + 4 * kq];
                fma2(acc[r], xv.x, w0);
                fma2(acc[r], xv.y, w1);
            }
        }
        float v[8];
#pragma unroll
        for (int r = 0; r < 8; r++) {
            float2 f = unpack2(acc[r]);
            v[r] = bsum + f.x + f.y;
        }
        float* d1 = &g_xg[(((size_t)t * 128 + (b0 >> 2)) * 512 + j) * 4];
        *(float4*)d1          = make_float4(v[0], v[1], v[2], v[3]);
        *(float4*)(d1 + 2048) = make_float4(v[4], v[5], v[6], v[7]);
        buf ^= 1;
    }
}

// =====================================================================
// MMA precompute v3 (layers 1-3): 16 batch cols per alo pass
// (4 B-fragments), direct coalesced g_xg stores, double-buffered B
// stage -> ONE barrier per tile.  (unchanged from R12)
// =====================================================================
__global__ __launch_bounds__(512, 1)
void precompute_mma_kernel(const float* __restrict__ Wih, int insel,
                           const float* __restrict__ bih,
                           const float* __restrict__ bhh)
{
    extern __shared__ char smraw[];
    char*     alo    = smraw;
    uint32_t* bstage = (uint32_t*)(smraw + PRE_BST_OFF);   // [2 buf][4 frag][512]

    const int j = threadIdx.x, w = j >> 5, l = j & 31;
    const int gid = l >> 2, qid = l & 3;
    const float* in = insel ? g_bufB : g_bufA;

    uint32_t wa[2][8][4];
    convert_weights_pre(Wih, alo, w, gid, qid, l, wa);

    float bs[2][2];
#pragma unroll
    for (int mt = 0; mt < 2; mt++) {
        int g0 = w * 32 + mt * 16 + gid;
        bs[mt][0] = bih[g0] + bhh[g0];
        bs[mt][1] = bih[g0 + 8] + bhh[g0 + 8];
    }

    const int ck = j & 127;
    const int cfr = j >> 7;
    uint32_t choff[4];
#pragma unroll
    for (int ci = 0; ci < 4; ci++) {
        uint32_t word = (ck >> 4) * 64 + ((ci * 4 + ((ck & 7) >> 1)) << 1)
                      + ((ck >> 3) & 1);
        choff[ci] = cfr * 2048 + word * 4 + (ck & 1) * 2;
    }

    const int NT = TSEQ * (NB / 16);
    const int stride = gridDim.x;

    {
        int t = blockIdx.x >> 5, b0 = (blockIdx.x & 31) * 16;
#pragma unroll
        for (int ci = 0; ci < 4; ci++) {
            float xv = in[((size_t)(b0 + cfr * 4 + ci) * TSEQ + t) * HID + ck];
            float hh = bf16_rn(xv);
            *(__nv_bfloat16*)((char*)bstage + choff[ci]) = __float2bfloat16(hh);
            *(__nv_bfloat16*)((char*)bstage + choff[ci] + 128) =
                __float2bfloat16(xv - hh);
        }
    }
    __syncthreads();

    int buf = 0;
    for (int tile = blockIdx.x; tile < NT; tile += stride) {
        const int t   = tile >> 5;
        const int bg0 = (tile & 31) * 4;

        float d[2][4][4];   // [mt][frag][q]
#pragma unroll
        for (int mt = 0; mt < 2; mt++)
#pragma unroll
            for (int f = 0; f < 4; f++) {
                if (qid < 2) {
                    d[mt][f][0] = bs[mt][0]; d[mt][f][1] = bs[mt][0];
                    d[mt][f][2] = bs[mt][1]; d[mt][f][3] = bs[mt][1];
                } else {
                    d[mt][f][0] = d[mt][f][1] = d[mt][f][2] = d[mt][f][3] = 0.f;
                }
            }

        int nxt = tile + stride;
        float xnext[4] = {0.f, 0.f, 0.f, 0.f};
        if (nxt < NT) {
            int tn = nxt >> 5, bn = (nxt & 31) * 16;
#pragma unroll
            for (int ci = 0; ci < 4; ci++)
                xnext[ci] = in[((size_t)(bn + cfr * 4 + ci) * TSEQ + tn) * HID + ck];
        }

        const uint32_t* bcur = bstage + buf * 2048;
#pragma unroll
        for (int kt = 0; kt < 8; kt++) {
            uint32_t bf[4][2];
#pragma unroll
            for (int f = 0; f < 4; f++) {
                uint2 v = *(const uint2*)&bcur[f * 512 + kt * 64 + 2 * l];
                bf[f][0] = v.x; bf[f][1] = v.y;
            }
            uint4 av0 = *(const uint4*)(alo + (((w * 2 + 0) * 8 + kt) * 32 + l) * 16);
            uint4 av1 = *(const uint4*)(alo + (((w * 2 + 1) * 8 + kt) * 32 + l) * 16);
#pragma unroll
            for (int f = 0; f < 4; f++) {
                mma16816(d[0][f], wa[0][kt], bf[f]);
                mma16816(d[1][f], wa[1][kt], bf[f]);
                mma16816(d[0][f], (const uint32_t*)&av0, bf[f]);
                mma16816(d[1][f], (const uint32_t*)&av1, bf[f]);
            }
        }

#pragma unroll
        for (int mt = 0; mt < 2; mt++)
#pragma unroll
            for (int f = 0; f < 4; f++)
#pragma unroll
                for (int q = 0; q < 4; q++)
                    d[mt][f][q] += __shfl_xor_sync(0xffffffffu, d[mt][f][q], 2);

        if (qid < 2) {
            int b = qid * 2;
#pragma unroll
            for (int mt = 0; mt < 2; mt++) {
                int g0 = w * 32 + mt * 16 + gid;
#pragma unroll
                for (int f = 0; f < 4; f++) {
                    float* dst = &g_xg[(((size_t)t * 128 + bg0 + f) * 512 + g0) * 4 + b];
                    *(float2*)dst        = make_float2(d[mt][f][0], d[mt][f][1]);
                    *(float2*)(dst + 32) = make_float2(d[mt][f][2], d[mt][f][3]);
                }
            }
        }

        {
            char* bnx = (char*)bstage + (buf ^ 1) * 8192;
#pragma unroll
            for (int ci = 0; ci < 4; ci++) {
                float nh = bf16_rn(xnext[ci]);
                *(__nv_bfloat16*)(bnx + choff[ci]) = __float2bfloat16(nh);
                *(__nv_bfloat16*)(bnx + choff[ci] + 128) =
                    __float2bfloat16(xnext[ci] - nh);
            }
        }
        __syncthreads();
        buf ^= 1;
    }
}

// =====================================================================
// MMA recurrent v7: 1024 threads, warp-team split of the two mt tiles.
// Warp w<16 -> tile 2w (mt=0), warp w>=16 -> tile 2(w-16)+1 (mt=1).
// Each warp: 16 HMMA/step, wa = 32 regs. 8 warps/SMSP for latency hiding.
// =====================================================================
__global__ __launch_bounds__(1024, 1)
void recurrent_kernel(const float* __restrict__ Whh, int outsel, int layer)
{
    extern __shared__ char smraw[];
    char*     alo    = smraw;
    uint32_t* bstage = (uint32_t*)(smraw + REC_BST_OFF);   // [2][512] words

    const int j = threadIdx.x, l = j & 31;
    const int w16 = (j >> 5) & 15;
    const int tm  = j >> 9;              // team 0/1
    const int tile = w16 * 2 + tm;       // 0..31
    const int gid = l >> 2, qid = l & 3;
    const int bgrp = blockIdx.x;
    const int b0 = bgrp * 4;
    float* out = outsel ? g_bufB : g_bufA;

    uint32_t wa[8][4];
    convert_weights_rec(Whh, alo, tile, gid, qid, l, wa);

    bstage[j] = 0;          // 1024 words = both buffers

    const int ulo = gid & 3;
    const int us  = tile * 4 + ulo;          // own unit
    const int cbs = 2 * qid + (gid >> 2);    // own batch col (valid qid<2)
    float c = 0.f;

    const int glo = (gid >> 2) * 128 + us;   // xg gate index (types 0/1 block)

    uint32_t bsh, bsl_;
    {
        uint32_t word = (us >> 4) * 64 + ((cbs * 4 + ((us & 7) >> 1)) << 1)
                      + ((us >> 3) & 1);
        bsh  = word * 4 + (us & 1) * 2;
        bsl_ = bsh + 128;
    }

    float2 xq[2];
    if (qid < 2) {
        const float* p = &g_xg[(size_t)bgrp * 2048 + glo * 4 + 2 * qid];
        xq[0] = *(const float2*)p;
        xq[1] = *(const float2*)(p + 1024);
    }
    __syncthreads();

    for (int t = 0; t < TSEQ; t++) {
        // split accumulator chains (hi / lo terms)
        float dh[4], dl[4];
        if (qid < 2) {
            dh[0] = xq[0].x; dh[1] = xq[0].y; dh[2] = xq[1].x; dh[3] = xq[1].y;
        } else {
            dh[0] = dh[1] = dh[2] = dh[3] = 0.f;
        }
        dl[0] = dl[1] = dl[2] = dl[3] = 0.f;

        // prefetch xg[t+1]
        {
            int tn = (t + 1 < TSEQ) ? (t + 1) : t;
            if (qid < 2) {
                const float* p = &g_xg[((size_t)tn * 128 + bgrp) * 2048 + glo * 4 + 2 * qid];
                xq[0] = *(const float2*)p;
                xq[1] = *(const float2*)(p + 1024);
            }
        }

        const uint32_t* bcur = bstage + (t & 1) * 512;
#pragma unroll
        for (int kt = 0; kt < 8; kt++) {
            uint2 bv = *(const uint2*)&bcur[kt * 64 + 2 * l];
            uint32_t bfr[2] = {bv.x, bv.y};
            uint4 av = *(const uint4*)(alo + ((tile * 8 + kt) * 32 + l) * 16);
            mma16816(dh, wa[kt], bfr);
            mma16816(dl, (const uint32_t*)&av, bfr);
        }

        // merge chains + pair hi/lo batch columns
        float dd[4], ee[4];
#pragma unroll
        for (int q = 0; q < 4; q++) {
            dd[q] = dh[q] + dl[q];
            dd[q] += __shfl_xor_sync(0xffffffffu, dd[q], 2);
        }
        // exchange gate-type blocks across gid^4 (lane^16)
#pragma unroll
        for (int q = 0; q < 4; q++)
            ee[q] = __shfl_xor_sync(0xffffffffu, dd[q], 16);

        char* bnx = (char*)bstage + ((t + 1) & 1) * 2048;
        if (qid < 2) {
            float pi, pf, pg, po;
            if (gid < 4) { pi = dd[0]; pf = ee[0]; pg = dd[2]; po = ee[2]; }
            else         { pi = ee[1]; pf = dd[1]; pg = ee[3]; po = dd[3]; }
            float iv = sigx(pi), fv = sigx(pf), gv = tanhx(pg), ov = sigx(po);
            c = fv * c + iv * gv;
            float h = ov * tanhx(c);
            out[((size_t)(b0 + cbs) * TSEQ + t) * HID + us] = h;
            if (t == TSEQ - 1)
                g_hN[layer * (NB * HID) + (b0 + cbs) * HID + us] = h;
            float hh = bf16_rn(h);
            *(__nv_bfloat16*)(bnx + bsh)  = __float2bfloat16(hh);
            *(__nv_bfloat16*)(bnx + bsl_) = __float2bfloat16(h - hh);
        }
        __syncthreads();   // h(t) published for step t+1
    }
}

// =====================================================================
// Heads: hN [4,512,128] -> (opt, tp, sl, lot), each [4,512,4]
// =====================================================================
__global__ void heads_kernel(
    const float* __restrict__ Wopt, const float* __restrict__ bopt,
    const float* __restrict__ Wlot, const float* __restrict__ blot,
    const float* __restrict__ Wtp,  const float* __restrict__ btp,
    const float* __restrict__ Wsl,  const float* __restrict__ bsl,
    float* __restrict__ outp)
{
    int tid = blockIdx.x * blockDim.x + threadIdx.x;
    if (tid >= 4 * 2048) return;
    int head = tid >> 11;
    int r    = tid & 2047;
    const float* W; const float* b;
    if      (head == 0) { W = Wopt; b = bopt; }
    else if (head == 1) { W = Wtp;  b = btp;  }
    else if (head == 2) { W = Wsl;  b = bsl;  }
    else                { W = Wlot; b = blot; }

    float y0 = b[0], y1 = b[1], y2 = b[2], y3 = b[3];
    const float4* hv = (const float4*)&g_hN[r * HID];
    const float4* w0 = (const float4*)&W[0];
    const float4* w1 = (const float4*)&W[128];
    const float4* w2 = (const float4*)&W[256];
    const float4* w3 = (const float4*)&W[384];
#pragma unroll 8
    for (int q = 0; q < 32; q++) {
        float4 h = hv[q];
        float4 a  = w0[q]; y0 += h.x*a.x  + h.y*a.y  + h.z*a.z  + h.w*a.w;
        float4 bq = w1[q]; y1 += h.x*bq.x + h.y*bq.y + h.z*bq.z + h.w*bq.w;
        float4 cq = w2[q]; y2 += h.x*cq.x + h.y*cq.y + h.z*cq.z + h.w*cq.w;
        float4 dq = w3[q]; y3 += h.x*dq.x + h.y*dq.y + h.z*dq.z + h.w*dq.w;
    }
    float o0, o1, o2, o3;
    if (head == 0) {
        float m = fmaxf(fmaxf(y0, y1), fmaxf(y2, y3));
        float e0 = __expf(y0 - m), e1 = __expf(y1 - m),
              e2 = __expf(y2 - m), e3 = __expf(y3 - m);
        float s = e0 + e1 + e2 + e3;
        float p0 = e0 / s, p1 = e1 / s, p2 = e2 / s, p3 = e3 / s;
        m = fmaxf(fmaxf(p0, p1), fmaxf(p2, p3));
        e0 = __expf(p0 - m); e1 = __expf(p1 - m);
        e2 = __expf(p2 - m); e3 = __expf(p3 - m);
        s = e0 + e1 + e2 + e3;
        o0 = e0 / s; o1 = e1 / s; o2 = e2 / s; o3 = e3 / s;
    } else {
        o0 = sigx(sigx(y0)); o1 = sigx(sigx(y1));
        o2 = sigx(sigx(y2)); o3 = sigx(sigx(y3));
    }
    float* dst = outp + head * 8192 + r * 4;
    dst[0] = o0; dst[1] = o1; dst[2] = o2; dst[3] = o3;
}

// =====================================================================
extern "C" void kernel_launch(void* const* d_in, const int* in_sizes, int n_in,
                              void* d_out, int out_size)
{
    const float* x      = (const float*)d_in[0];
    const float* Wih0   = (const float*)d_in[1];
    const float* Whh0   = (const float*)d_in[2];
    const float* bih0   = (const float*)d_in[3];
    const float* bhh0   = (const float*)d_in[4];
    const float* Wih123 = (const float*)d_in[5];
    const float* Whh123 = (const float*)d_in[6];
    const float* bih123 = (const float*)d_in[7];
    const float* bhh123 = (const float*)d_in[8];
    const float* Wopt   = (const float*)d_in[9];
    const float* bopt   = (const float*)d_in[10];
    const float* Wlot   = (const float*)d_in[11];
    const float* blot   = (const float*)d_in[12];
    const float* Wtp    = (const float*)d_in[13];
    const float* btp    = (const float*)d_in[14];
    const float* Wsl    = (const float*)d_in[15];
    const float* bsl    = (const float*)d_in[16];
    float* outp = (float*)d_out;

    const int SM_PRE32 = 2 * 8 * 32 * 4;   // 2048

    cudaFuncSetAttribute(recurrent_kernel,
                         cudaFuncAttributeMaxDynamicSharedMemorySize, REC_SMEM);
    cudaFuncSetAttribute(precompute_mma_kernel,
                         cudaFuncAttributeMaxDynamicSharedMemorySize, PRE_SMEM);

    // layer 0
    precompute_kernel<32><<<148, 512, SM_PRE32>>>(x, Wih0, bih0, bhh0);
    recurrent_kernel<<<128, 1024, REC_SMEM>>>(Whh0, /*out=A*/0, /*layer*/0);
    // layer 1 (in A -> out B)
    precompute_mma_kernel<<<148, 512, PRE_SMEM>>>(Wih123 + 0 * G4 * HID, 0,
        bih123 + 0 * G4, bhh123 + 0 * G4);
    recurrent_kernel<<<128, 1024, REC_SMEM>>>(Whh123 + 0 * G4 * HID, 1, 1);
    // layer 2 (in B -> out A)
    precompute_mma_kernel<<<148, 512, PRE_SMEM>>>(Wih123 + 1 * G4 * HID, 1,
        bih123 + 1 * G4, bhh123 + 1 * G4);
    recurrent_kernel<<<128, 1024, REC_SMEM>>>(Whh123 + 1 * G4 * HID, 0, 2);
    // layer 3 (in A -> out B)
    precompute_mma_kernel<<<148, 512, PRE_SMEM>>>(Wih123 + 2 * G4 * HID, 0,
        bih123 + 2 * G4, bhh123 + 2 * G4);
    recurrent_kernel<<<128, 1024, REC_SMEM>>>(Whh123 + 2 * G4 * HID, 1, 3);
    // heads
    heads_kernel<<<(4 * 2048 + 255) / 256, 256>>>(
        Wopt, bopt, Wlot, blot, Wtp, btp, Wsl, bsl, outp);
}

// round 14
// speedup vs baseline: 1.2270x; 1.2270x over previous
#include <cuda_runtime.h>
#include <cuda_bf16.h>
#include <cstdint>
#include <cstddef>

#define TSEQ 912
#define NB   512
#define HID  128
#define G4   512   // 4*H

typedef unsigned long long ull;

// ---------------- device scratch (static, allowed) ----------------
// layout: [t][bgrp (NB/4)][gate (512)][4 batch]
__device__ float g_xg[(size_t)TSEQ * (NB / 4) * G4 * 4];
__device__ float g_bufA[(size_t)NB * TSEQ * HID];   // [b][t][u]
__device__ float g_bufB[(size_t)NB * TSEQ * HID];
__device__ float g_hN[4 * NB * HID];                // [layer][b][u]

// ---------------- f32x2 helpers (layer-0 precompute) ----------------
__device__ __forceinline__ ull pack2(float lo, float hi) {
    ull r;
    asm("mov.b64 %0, {%1, %2};" : "=l"(r)
        : "r"(__float_as_uint(lo)), "r"(__float_as_uint(hi)));
    return r;
}
__device__ __forceinline__ float2 unpack2(ull v) {
    unsigned lo, hi;
    asm("mov.b64 {%0, %1}, %2;" : "=r"(lo), "=r"(hi) : "l"(v));
    return make_float2(__uint_as_float(lo), __uint_as_float(hi));
}
__device__ __forceinline__ void fma2(ull& d, ull a, ull b) {
    asm("fma.rn.f32x2 %0, %1, %2, %0;" : "+l"(d) : "l"(a), "l"(b));
}

// ---------------- activations ----------------
__device__ __forceinline__ float sigx(float x) {
    x = fminf(fmaxf(x, -30.f), 30.f);
    return __fdividef(1.f, 1.f + __expf(-x));
}
__device__ __forceinline__ float tanhx(float x) {
    x = fminf(fmaxf(x, -15.f), 15.f);
    float e = __expf(2.f * x);
    return __fdividef(e - 1.f, e + 1.f);
}

// ---------------- bf16 helpers ----------------
__device__ __forceinline__ float bf16_rn(float x) {
    return __bfloat162float(__float2bfloat16(x));
}
__device__ __forceinline__ uint32_t pack_bf16x2(float a, float b) {
    uint32_t r;
    asm("cvt.rn.bf16x2.f32 %0, %1, %2;" : "=r"(r) : "f"(b), "f"(a));
    return r;
}

// ---------------- cp.async helpers (layer-0 precompute) ----------------
__device__ __forceinline__ unsigned smem_u32(const void* p) {
    return (unsigned)__cvta_generic_to_shared(p);
}
__device__ __forceinline__ void cpasync16(unsigned saddr, const void* gaddr) {
    asm volatile("cp.async.ca.shared.global [%0], [%1], 16;"
                 :: "r"(saddr), "l"(gaddr));
}
__device__ __forceinline__ void cpasync_commit() {
    asm volatile("cp.async.commit_group;");
}
__device__ __forceinline__ void cpasync_wait0() {
    asm volatile("cp.async.wait_group 0;");
}

// ---------------- warp mma m16n8k16 bf16 ----------------
__device__ __forceinline__ void mma16816(float* d, const uint32_t* a,
                                         const uint32_t* b) {
    asm volatile(
        "mma.sync.aligned.m16n8k16.row.col.f32.bf16.bf16.f32 "
        "{%0,%1,%2,%3}, {%4,%5,%6,%7}, {%8,%9}, {%0,%1,%2,%3};"
        : "+f"(d[0]), "+f"(d[1]), "+f"(d[2]), "+f"(d[3])
        : "r"(a[0]), "r"(a[1]), "r"(a[2]), "r"(a[3]), "r"(b[0]), "r"(b[1]));
}

// shared layouts:
// recurrent: full alo (128 KB) + 2x512-word B stage  (R12 proven form)
#define REC_BST_OFF  131072
#define REC_SMEM     (131072 + 4096)         // 135168
// precompute v4: half alo (64 KB, 256 gates) + 2 buf x 4 frag x 512 words
#define PRE_BST_OFF  65536
#define PRE_SMEM     (65536 + 16384)         // 81920  -> 2 CTAs/SM

// ---- recurrent weight conversion (512 thr, 2 tiles/warp, reordered) ----
__device__ __forceinline__ void convert_weights_rec(
    const float* __restrict__ W, char* alo, int w, int gid, int qid, int l,
    uint32_t wa[2][8][4])
{
#pragma unroll
    for (int mt = 0; mt < 2; mt++) {
#pragma unroll
        for (int kt = 0; kt < 8; kt++) {
            uint32_t lo4[4];
#pragma unroll
            for (int q = 0; q < 4; q++) {
                int rf = gid + (q & 1) * 8;
                int row = (rf >> 2) * 128 + w * 8 + mt * 4 + (rf & 3);
                int col = kt * 16 + qid * 2 + (q >> 1) * 8;
                float w0 = W[row * 128 + col];
                float w1 = W[row * 128 + col + 1];
                float h0 = bf16_rn(w0), h1 = bf16_rn(w1);
                wa[mt][kt][q] = pack_bf16x2(h0, h1);
                lo4[q] = pack_bf16x2(w0 - h0, w1 - h1);
            }
            *(uint4*)(alo + (((w * 2 + mt) * 8 + kt) * 32 + l) * 16) =
                make_uint4(lo4[0], lo4[1], lo4[2], lo4[3]);
        }
    }
}

// ---- precompute weight conversion (256 thr, gate half gh) ----
__device__ __forceinline__ void convert_weights_pre(
    const float* __restrict__ W, char* alo, int gh, int w, int gid, int qid,
    int l, uint32_t wa[2][8][4])
{
#pragma unroll
    for (int mt = 0; mt < 2; mt++) {
#pragma unroll
        for (int kt = 0; kt < 8; kt++) {
            uint32_t lo4[4];
#pragma unroll
            for (int q = 0; q < 4; q++) {
                int rf = gid + (q & 1) * 8;
                int row = gh * 256 + w * 32 + mt * 16 + rf;
                int col = kt * 16 + qid * 2 + (q >> 1) * 8;
                float w0 = W[row * 128 + col];
                float w1 = W[row * 128 + col + 1];
                float h0 = bf16_rn(w0), h1 = bf16_rn(w1);
                wa[mt][kt][q] = pack_bf16x2(h0, h1);
                lo4[q] = pack_bf16x2(w0 - h0, w1 - h1);
            }
            *(uint4*)(alo + (((w * 2 + mt) * 8 + kt) * 32 + l) * 16) =
                make_uint4(lo4[0], lo4[1], lo4[2], lo4[3]);
        }
    }
}

// =====================================================================
// Layer-0 precompute (K=32, fp32 FFMA path)
// =====================================================================
template<int K>
__global__ __launch_bounds__(512, 1)
void precompute_kernel(const float* __restrict__ xext,
                       const float* __restrict__ Wih,
                       const float* __restrict__ bih,
                       const float* __restrict__ bhh)
{
    extern __shared__ float sm[];
    constexpr int CHUNKS = 8 * K / 4;
    float* xt = sm;                              // [2][8][K]

    const int j = threadIdx.x;
    const float* in = xext;

    ull wregp[K / 2];
#pragma unroll
    for (int kk = 0; kk < K / 2; kk++)
        wregp[kk] = pack2(Wih[j * K + 2 * kk], Wih[j * K + 2 * kk + 1]);
    const float bsum = bih[j] + bhh[j];

    const unsigned xt_s = smem_u32(xt);
    const int NT = TSEQ * (NB / 8);
    const int stride = gridDim.x;

    int tile0 = blockIdx.x;
    if (tile0 < NT && j < CHUNKS) {
        int t  = tile0 >> 6;
        int b0 = (tile0 & 63) << 3;
        int r  = j / (K / 4), kk = j % (K / 4);
        cpasync16(xt_s + (unsigned)(r * K + kk * 4) * 4,
                  &in[((size_t)(b0 + r) * TSEQ + t) * K + kk * 4]);
    }
    cpasync_commit();

    int buf = 0;
    for (int tile = blockIdx.x; tile < NT; tile += stride) {
        cpasync_wait0();
        __syncthreads();

        int nxt = tile + stride;
        if (nxt < NT && j < CHUNKS) {
            int tn  = nxt >> 6;
            int bn0 = (nxt & 63) << 3;
            int r   = j / (K / 4), kk = j % (K / 4);
            cpasync16(xt_s + (unsigned)((buf ^ 1) * 8 * K + r * K + kk * 4) * 4,
                      &in[((size_t)(bn0 + r) * TSEQ + tn) * K + kk * 4]);
        }
        cpasync_commit();

        const float* xtb = xt + buf * 8 * K;
        const int t  = tile >> 6;
        const int b0 = (tile & 63) << 3;

        ull acc[8] = {0, 0, 0, 0, 0, 0, 0, 0};
#pragma unroll
        for (int kq = 0; kq < K / 4; kq++) {
            ull w0 = wregp[2 * kq], w1 = wregp[2 * kq + 1];
#pragma unroll
            for (int r = 0; r < 8; r++) {
                ulonglong2 xv = *(const ulonglong2*)&xtb[r * K + 4 * kq];
                fma2(acc[r], xv.x, w0);
                fma2(acc[r], xv.y, w1);
            }
        }
        float v[8];
#pragma unroll
        for (int r = 0; r < 8; r++) {
            float2 f = unpack2(acc[r]);
            v[r] = bsum + f.x + f.y;
        }
        float* d1 = &g_xg[(((size_t)t * 128 + (b0 >> 2)) * 512 + j) * 4];
        *(float4*)d1          = make_float4(v[0], v[1], v[2], v[3]);
        *(float4*)(d1 + 2048) = make_float4(v[4], v[5], v[6], v[7]);
        buf ^= 1;
    }
}

// =====================================================================
// MMA precompute v4 (layers 1-3): 256 threads, gate half per block,
// 64 KB alo -> 2 CTAs/SM for cross-CTA latency overlap.
// gh = blockIdx&1; tiles strided by gridDim/2. 16 batch cols per tile.
// =====================================================================
__global__ __launch_bounds__(256, 2)
void precompute_mma_kernel(const float* __restrict__ Wih, int insel,
                           const float* __restrict__ bih,
                           const float* __restrict__ bhh)
{
    extern __shared__ char smraw[];
    char*     alo    = smraw;                              // 64 KB
    uint32_t* bstage = (uint32_t*)(smraw + PRE_BST_OFF);   // [2 buf][4 frag][512]

    const int j = threadIdx.x, w = j >> 5, l = j & 31;     // w: 0..7
    const int gid = l >> 2, qid = l & 3;
    const int gh = blockIdx.x & 1;
    const float* in = insel ? g_bufB : g_bufA;

    uint32_t wa[2][8][4];
    convert_weights_pre(Wih, alo, gh, w, gid, qid, l, wa);

    float bs[2][2];
#pragma unroll
    for (int mt = 0; mt < 2; mt++) {
        int g0 = gh * 256 + w * 32 + mt * 16 + gid;
        bs[mt][0] = bih[g0] + bhh[g0];
        bs[mt][1] = bih[g0 + 8] + bhh[g0 + 8];
    }

    // staging role: thread j -> (k = ck, frags cf0, cf0+1; 4 cols each)
    const int ck  = j & 127;
    const int cf0 = (j >> 7) * 2;           // 0 or 2
    uint32_t choff[2][4];
#pragma unroll
    for (int fi = 0; fi < 2; fi++)
#pragma unroll
        for (int ci = 0; ci < 4; ci++) {
            uint32_t word = (ck >> 4) * 64 + ((ci * 4 + ((ck & 7) >> 1)) << 1)
                          + ((ck >> 3) & 1);
            choff[fi][ci] = (cf0 + fi) * 2048 + word * 4 + (ck & 1) * 2;
        }

    const int NT = TSEQ * (NB / 16);
    const int stride = (int)(gridDim.x >> 1);

    // prologue: stage first tile's inputs into buffer 0
    {
        int tile0 = (int)(blockIdx.x >> 1);
        int t = tile0 >> 5, b0 = (tile0 & 31) * 16;
#pragma unroll
        for (int fi = 0; fi < 2; fi++)
#pragma unroll
            for (int ci = 0; ci < 4; ci++) {
                float xv = in[((size_t)(b0 + (cf0 + fi) * 4 + ci) * TSEQ + t) * HID + ck];
                float hh = bf16_rn(xv);
                *(__nv_bfloat16*)((char*)bstage + choff[fi][ci]) = __float2bfloat16(hh);
                *(__nv_bfloat16*)((char*)bstage + choff[fi][ci] + 128) =
                    __float2bfloat16(xv - hh);
            }
    }
    __syncthreads();

    int buf = 0;
    for (int tile = (int)(blockIdx.x >> 1); tile < NT; tile += stride) {
        const int t   = tile >> 5;
        const int bg0 = (tile & 31) * 4;

        float d[2][4][4];   // [mt][frag][q]
#pragma unroll
        for (int mt = 0; mt < 2; mt++)
#pragma unroll
            for (int f = 0; f < 4; f++) {
                if (qid < 2) {
                    d[mt][f][0] = bs[mt][0]; d[mt][f][1] = bs[mt][0];
                    d[mt][f][2] = bs[mt][1]; d[mt][f][3] = bs[mt][1];
                } else {
                    d[mt][f][0] = d[mt][f][1] = d[mt][f][2] = d[mt][f][3] = 0.f;
                }
            }

        int nxt = tile + stride;
        float xnext[2][4];
#pragma unroll
        for (int fi = 0; fi < 2; fi++)
#pragma unroll
            for (int ci = 0; ci < 4; ci++) xnext[fi][ci] = 0.f;
        if (nxt < NT) {
            int tn = nxt >> 5, bn = (nxt & 31) * 16;
#pragma unroll
            for (int fi = 0; fi < 2; fi++)
#pragma unroll
                for (int ci = 0; ci < 4; ci++)
                    xnext[fi][ci] =
                        in[((size_t)(bn + (cf0 + fi) * 4 + ci) * TSEQ + tn) * HID + ck];
        }

        const uint32_t* bcur = bstage + buf * 2048;
#pragma unroll
        for (int kt = 0; kt < 8; kt++) {
            uint32_t bf[4][2];
#pragma unroll
            for (int f = 0; f < 4; f++) {
                uint2 v = *(const uint2*)&bcur[f * 512 + kt * 64 + 2 * l];
                bf[f][0] = v.x; bf[f][1] = v.y;
            }
            uint4 av0 = *(const uint4*)(alo + (((w * 2 + 0) * 8 + kt) * 32 + l) * 16);
            uint4 av1 = *(const uint4*)(alo + (((w * 2 + 1) * 8 + kt) * 32 + l) * 16);
#pragma unroll
            for (int f = 0; f < 4; f++) {
                mma16816(d[0][f], wa[0][kt], bf[f]);
                mma16816(d[1][f], wa[1][kt], bf[f]);
                mma16816(d[0][f], (const uint32_t*)&av0, bf[f]);
                mma16816(d[1][f], (const uint32_t*)&av1, bf[f]);
            }
        }

#pragma unroll
        for (int mt = 0; mt < 2; mt++)
#pragma unroll
            for (int f = 0; f < 4; f++)
#pragma unroll
                for (int q = 0; q < 4; q++)
                    d[mt][f][q] += __shfl_xor_sync(0xffffffffu, d[mt][f][q], 2);

        // direct coalesced stores to g_xg (gate half gh)
        if (qid < 2) {
            int b = qid * 2;
#pragma unroll
            for (int mt = 0; mt < 2; mt++) {
                int g0 = gh * 256 + w * 32 + mt * 16 + gid;
#pragma unroll
                for (int f = 0; f < 4; f++) {
                    float* dst = &g_xg[(((size_t)t * 128 + bg0 + f) * 512 + g0) * 4 + b];
                    *(float2*)dst        = make_float2(d[mt][f][0], d[mt][f][1]);
                    *(float2*)(dst + 32) = make_float2(d[mt][f][2], d[mt][f][3]);
                }
            }
        }

        // convert next tile's inputs into the other buffer
        {
            char* bnx = (char*)bstage + (buf ^ 1) * 8192;
#pragma unroll
            for (int fi = 0; fi < 2; fi++)
#pragma unroll
                for (int ci = 0; ci < 4; ci++) {
                    float nh = bf16_rn(xnext[fi][ci]);
                    *(__nv_bfloat16*)(bnx + choff[fi][ci]) = __float2bfloat16(nh);
                    *(__nv_bfloat16*)(bnx + choff[fi][ci] + 128) =
                        __float2bfloat16(xnext[fi][ci] - nh);
                }
        }
        __syncthreads();
        buf ^= 1;
    }
}

// =====================================================================
// MMA recurrent (R12 proven form): 512 threads, split chains +
// full-warp tail, one barrier per step.
// =====================================================================
__global__ __launch_bounds__(512, 1)
void recurrent_kernel(const float* __restrict__ Whh, int outsel, int layer)
{
    extern __shared__ char smraw[];
    char*     alo    = smraw;
    uint32_t* bstage = (uint32_t*)(smraw + REC_BST_OFF);   // [2][512] words

    const int j = threadIdx.x, w = j >> 5, l = j & 31;
    const int gid = l >> 2, qid = l & 3;
    const int bgrp = blockIdx.x;
    const int b0 = bgrp * 4;
    float* out = outsel ? g_bufB : g_bufA;

    uint32_t wa[2][8][4];
    convert_weights_rec(Whh, alo, w, gid, qid, l, wa);

    bstage[j] = 0;
    bstage[j + 512] = 0;

    // per-thread cell role (post-pairing)
    const int mts = qid >> 1;
    const int qd  = qid & 1;
    const int ulo = gid & 3;
    const int cbs = 2 * qd + (gid >> 2);
    const int us  = w * 8 + mts * 4 + ulo;
    float c = 0.f;

    const int glo0 = (gid >> 2) * 128 + w * 8 + 0 * 4 + ulo;
    const int glo1 = glo0 + 4;

    uint32_t bsh, bsl_;
    {
        uint32_t word = (us >> 4) * 64 + ((cbs * 4 + ((us & 7) >> 1)) << 1)
                      + ((us >> 3) & 1);
        bsh  = word * 4 + (us & 1) * 2;
        bsl_ = bsh + 128;
    }

    float2 xq[2][2];
    if (qid < 2) {
        const float* p0 = &g_xg[((size_t)0 + bgrp) * 2048 + glo0 * 4 + 2 * qid];
        xq[0][0] = *(const float2*)p0;
        xq[0][1] = *(const float2*)(p0 + 1024);
        const float* p1 = &g_xg[((size_t)0 + bgrp) * 2048 + glo1 * 4 + 2 * qid];
        xq[1][0] = *(const float2*)p1;
        xq[1][1] = *(const float2*)(p1 + 1024);
    }
    __syncthreads();

    for (int t = 0; t < TSEQ; t++) {
        float dh[2][4], dl[2][4];
#pragma unroll
        for (int mt = 0; mt < 2; mt++) {
            if (qid < 2) {
                dh[mt][0] = xq[mt][0].x; dh[mt][1] = xq[mt][0].y;
                dh[mt][2] = xq[mt][1].x; dh[mt][3] = xq[mt][1].y;
            } else {
                dh[mt][0] = dh[mt][1] = dh[mt][2] = dh[mt][3] = 0.f;
            }
            dl[mt][0] = dl[mt][1] = dl[mt][2] = dl[mt][3] = 0.f;
        }

        {
            int tn = (t + 1 < TSEQ) ? (t + 1) : t;
            if (qid < 2) {
                const float* p0 = &g_xg[((size_t)tn * 128 + bgrp) * 2048 + glo0 * 4 + 2 * qid];
                xq[0][0] = *(const float2*)p0;
                xq[0][1] = *(const float2*)(p0 + 1024);
                const float* p1 = &g_xg[((size_t)tn * 128 + bgrp) * 2048 + glo1 * 4 + 2 * qid];
                xq[1][0] = *(const float2*)p1;
                xq[1][1] = *(const float2*)(p1 + 1024);
            }
        }

        const uint32_t* bcur = bstage + (t & 1) * 512;
#pragma unroll
        for (int kt = 0; kt < 8; kt++) {
            uint2 bv = *(const uint2*)&bcur[kt * 64 + 2 * l];
            uint32_t bfr[2] = {bv.x, bv.y};
            uint4 av0 = *(const uint4*)(alo + (((w * 2 + 0) * 8 + kt) * 32 + l) * 16);
            uint4 av1 = *(const uint4*)(alo + (((w * 2 + 1) * 8 + kt) * 32 + l) * 16);
            mma16816(dh[0], wa[0][kt], bfr);
            mma16816(dh[1], wa[1][kt], bfr);
            mma16816(dl[0], (const uint32_t*)&av0, bfr);
            mma16816(dl[1], (const uint32_t*)&av1, bfr);
        }

        float dd[4], ee[4];
#pragma unroll
        for (int q = 0; q < 4; q++) {
            float d0 = dh[0][q] + dl[0][q];
            float d1 = dh[1][q] + dl[1][q];
            float own  = mts ? d1 : d0;
            float send = mts ? d0 : d1;
            dd[q] = own + __shfl_xor_sync(0xffffffffu, send, 2);
        }
#pragma unroll
        for (int q = 0; q < 4; q++)
            ee[q] = __shfl_xor_sync(0xffffffffu, dd[q], 16);

        {
            float pi, pf, pg, po;
            if (gid < 4) { pi = dd[0]; pf = ee[0]; pg = dd[2]; po = ee[2]; }
            else         { pi = ee[1]; pf = dd[1]; pg = ee[3]; po = dd[3]; }
            float iv = sigx(pi), fv = sigx(pf), gv = tanhx(pg), ov = sigx(po);
            c = fv * c + iv * gv;
            float h = ov * tanhx(c);
            out[((size_t)(b0 + cbs) * TSEQ + t) * HID + us] = h;
            if (t == TSEQ - 1)
                g_hN[layer * (NB * HID) + (b0 + cbs) * HID + us] = h;
            float hh = bf16_rn(h);
            char* bnx = (char*)bstage + ((t + 1) & 1) * 2048;
            *(__nv_bfloat16*)(bnx + bsh)  = __float2bfloat16(hh);
            *(__nv_bfloat16*)(bnx + bsl_) = __float2bfloat16(h - hh);
        }
        __syncthreads();   // h(t) published for step t+1
    }
}

// =====================================================================
// Heads: hN [4,512,128] -> (opt, tp, sl, lot), each [4,512,4]
// =====================================================================
__global__ void heads_kernel(
    const float* __restrict__ Wopt, const float* __restrict__ bopt,
    const float* __restrict__ Wlot, const float* __restrict__ blot,
    const float* __restrict__ Wtp,  const float* __restrict__ btp,
    const float* __restrict__ Wsl,  const float* __restrict__ bsl,
    float* __restrict__ outp)
{
    int tid = blockIdx.x * blockDim.x + threadIdx.x;
    if (tid >= 4 * 2048) return;
    int head = tid >> 11;
    int r    = tid & 2047;
    const float* W; const float* b;
    if      (head == 0) { W = Wopt; b = bopt; }
    else if (head == 1) { W = Wtp;  b = btp;  }
    else if (head == 2) { W = Wsl;  b = bsl;  }
    else                { W = Wlot; b = blot; }

    float y0 = b[0], y1 = b[1], y2 = b[2], y3 = b[3];
    const float4* hv = (const float4*)&g_hN[r * HID];
    const float4* w0 = (const float4*)&W[0];
    const float4* w1 = (const float4*)&W[128];
    const float4* w2 = (const float4*)&W[256];
    const float4* w3 = (const float4*)&W[384];
#pragma unroll 8
    for (int q = 0; q < 32; q++) {
        float4 h = hv[q];
        float4 a  = w0[q]; y0 += h.x*a.x  + h.y*a.y  + h.z*a.z  + h.w*a.w;
        float4 bq = w1[q]; y1 += h.x*bq.x + h.y*bq.y + h.z*bq.z + h.w*bq.w;
        float4 cq = w2[q]; y2 += h.x*cq.x + h.y*cq.y + h.z*cq.z + h.w*cq.w;
        float4 dq = w3[q]; y3 += h.x*dq.x + h.y*dq.y + h.z*dq.z + h.w*dq.w;
    }
    float o0, o1, o2, o3;
    if (head == 0) {
        float m = fmaxf(fmaxf(y0, y1), fmaxf(y2, y3));
        float e0 = __expf(y0 - m), e1 = __expf(y1 - m),
              e2 = __expf(y2 - m), e3 = __expf(y3 - m);
        float s = e0 + e1 + e2 + e3;
        float p0 = e0 / s, p1 = e1 / s, p2 = e2 / s, p3 = e3 / s;
        m = fmaxf(fmaxf(p0, p1), fmaxf(p2, p3));
        e0 = __expf(p0 - m); e1 = __expf(p1 - m);
        e2 = __expf(p2 - m); e3 = __expf(p3 - m);
        s = e0 + e1 + e2 + e3;
        o0 = e0 / s; o1 = e1 / s; o2 = e2 / s; o3 = e3 / s;
    } else {
        o0 = sigx(sigx(y0)); o1 = sigx(sigx(y1));
        o2 = sigx(sigx(y2)); o3 = sigx(sigx(y3));
    }
    float* dst = outp + head * 8192 + r * 4;
    dst[0] = o0; dst[1] = o1; dst[2] = o2; dst[3] = o3;
}

// =====================================================================
extern "C" void kernel_launch(void* const* d_in, const int* in_sizes, int n_in,
                              void* d_out, int out_size)
{
    const float* x      = (const float*)d_in[0];
    const float* Wih0   = (const float*)d_in[1];
    const float* Whh0   = (const float*)d_in[2];
    const float* bih0   = (const float*)d_in[3];
    const float* bhh0   = (const float*)d_in[4];
    const float* Wih123 = (const float*)d_in[5];
    const float* Whh123 = (const float*)d_in[6];
    const float* bih123 = (const float*)d_in[7];
    const float* bhh123 = (const float*)d_in[8];
    const float* Wopt   = (const float*)d_in[9];
    const float* bopt   = (const float*)d_in[10];
    const float* Wlot   = (const float*)d_in[11];
    const float* blot   = (const float*)d_in[12];
    const float* Wtp    = (const float*)d_in[13];
    const float* btp    = (const float*)d_in[14];
    const float* Wsl    = (const float*)d_in[15];
    const float* bsl    = (const float*)d_in[16];
    float* outp = (float*)d_out;

    const int SM_PRE32 = 2 * 8 * 32 * 4;   // 2048

    cudaFuncSetAttribute(recurrent_kernel,
                         cudaFuncAttributeMaxDynamicSharedMemorySize, REC_SMEM);
    cudaFuncSetAttribute(precompute_mma_kernel,
                         cudaFuncAttributeMaxDynamicSharedMemorySize, PRE_SMEM);

    // layer 0
    precompute_kernel<32><<<148, 512, SM_PRE32>>>(x, Wih0, bih0, bhh0);
    recurrent_kernel<<<128, 512, REC_SMEM>>>(Whh0, /*out=A*/0, /*layer*/0);
    // layer 1 (in A -> out B)
    precompute_mma_kernel<<<296, 256, PRE_SMEM>>>(Wih123 + 0 * G4 * HID, 0,
        bih123 + 0 * G4, bhh123 + 0 * G4);
    recurrent_kernel<<<128, 512, REC_SMEM>>>(Whh123 + 0 * G4 * HID, 1, 1);
    // layer 2 (in B -> out A)
    precompute_mma_kernel<<<296, 256, PRE_SMEM>>>(Wih123 + 1 * G4 * HID, 1,
        bih123 + 1 * G4, bhh123 + 1 * G4);
    recurrent_kernel<<<128, 512, REC_SMEM>>>(Whh123 + 1 * G4 * HID, 0, 2);
    // layer 3 (in A -> out B)
    precompute_mma_kernel<<<296, 256, PRE_SMEM>>>(Wih123 + 2 * G4 * HID, 0,
        bih123 + 2 * G4, bhh123 + 2 * G4);
    recurrent_kernel<<<128, 512, REC_SMEM>>>(Whh123 + 2 * G4 * HID, 1, 3);
    // heads
    heads_kernel<<<(4 * 2048 + 255) / 256, 256>>>(
        Wopt, bopt, Wlot, blot, Wtp, btp, Wsl, bsl, outp);
}

// round 15
// speedup vs baseline: 1.3261x; 1.0808x over previous
#include <cuda_runtime.h>
#include <cuda_bf16.h>
#include <cstdint>
#include <cstddef>

#define TSEQ 912
#define NB   512
#define HID  128
#define G4   512   // 4*H

typedef unsigned long long ull;

// ---------------- device scratch (static, allowed) ----------------
// layout: [t][bgrp (NB/4)][gate (512)][4 batch]
__device__ float g_xg[(size_t)TSEQ * (NB / 4) * G4 * 4];
__device__ float g_bufA[(size_t)NB * TSEQ * HID];   // [b][t][u]
__device__ float g_bufB[(size_t)NB * TSEQ * HID];
__device__ float g_hN[4 * NB * HID];                // [layer][b][u]

// ---------------- f32x2 helpers (layer-0 precompute) ----------------
__device__ __forceinline__ ull pack2(float lo, float hi) {
    ull r;
    asm("mov.b64 %0, {%1, %2};" : "=l"(r)
        : "r"(__float_as_uint(lo)), "r"(__float_as_uint(hi)));
    return r;
}
__device__ __forceinline__ float2 unpack2(ull v) {
    unsigned lo, hi;
    asm("mov.b64 {%0, %1}, %2;" : "=r"(lo), "=r"(hi) : "l"(v));
    return make_float2(__uint_as_float(lo), __uint_as_float(hi));
}
__device__ __forceinline__ void fma2(ull& d, ull a, ull b) {
    asm("fma.rn.f32x2 %0, %1, %2, %0;" : "+l"(d) : "l"(a), "l"(b));
}

// ---------------- activations ----------------
// precise versions (heads kernel)
__device__ __forceinline__ float sigx(float x) {
    x = fminf(fmaxf(x, -30.f), 30.f);
    return __fdividef(1.f, 1.f + __expf(-x));
}
__device__ __forceinline__ float tanhx(float x) {
    x = fminf(fmaxf(x, -15.f), 15.f);
    float e = __expf(2.f * x);
    return __fdividef(e - 1.f, e + 1.f);
}
// fast versions (recurrent kernel): single MUFU.TANH
__device__ __forceinline__ float tanh_fast(float x) {
    float r;
    asm("tanh.approx.f32 %0, %1;" : "=f"(r) : "f"(x));
    return r;
}
__device__ __forceinline__ float sig_fast(float x) {
    return fmaf(0.5f, tanh_fast(0.5f * x), 0.5f);
}

// ---------------- bf16 helpers ----------------
__device__ __forceinline__ float bf16_rn(float x) {
    return __bfloat162float(__float2bfloat16(x));
}
__device__ __forceinline__ uint32_t pack_bf16x2(float a, float b) {
    uint32_t r;
    asm("cvt.rn.bf16x2.f32 %0, %1, %2;" : "=r"(r) : "f"(b), "f"(a));
    return r;
}

// ---------------- cp.async helpers (layer-0 precompute) ----------------
__device__ __forceinline__ unsigned smem_u32(const void* p) {
    return (unsigned)__cvta_generic_to_shared(p);
}
__device__ __forceinline__ void cpasync16(unsigned saddr, const void* gaddr) {
    asm volatile("cp.async.ca.shared.global [%0], [%1], 16;"
                 :: "r"(saddr), "l"(gaddr));
}
__device__ __forceinline__ void cpasync_commit() {
    asm volatile("cp.async.commit_group;");
}
__device__ __forceinline__ void cpasync_wait0() {
    asm volatile("cp.async.wait_group 0;");
}

// ---------------- warp mma m16n8k16 bf16 ----------------
__device__ __forceinline__ void mma16816(float* d, const uint32_t* a,
                                         const uint32_t* b) {
    asm volatile(
        "mma.sync.aligned.m16n8k16.row.col.f32.bf16.bf16.f32 "
        "{%0,%1,%2,%3}, {%4,%5,%6,%7}, {%8,%9}, {%0,%1,%2,%3};"
        : "+f"(d[0]), "+f"(d[1]), "+f"(d[2]), "+f"(d[3])
        : "r"(a[0]), "r"(a[1]), "r"(a[2]), "r"(a[3]), "r"(b[0]), "r"(b[1]));
}

// shared layouts:
// recurrent: full alo (128 KB) + 2x512-word B stage
#define REC_BST_OFF  131072
#define REC_SMEM     (131072 + 4096)         // 135168
// precompute: full alo (128 KB) + 2 buf x 4 frag x 512-word B stage
#define PRE_BST_OFF  131072
#define PRE_SMEM     (131072 + 16384)        // 147456

// convert fp32 weights [512][128] -> Whi regs + Wlo smem fragments.
// REORDER=true (recurrent): row = (rf>>2)*128 + w*8 + mt*4 + (rf&3)
// REORDER=false (precompute): row = w*32 + mt*16 + rf
template<bool REORDER>
__device__ __forceinline__ void convert_weights(
    const float* __restrict__ W, char* alo, int w, int gid, int qid, int l,
    uint32_t wa[2][8][4])
{
#pragma unroll
    for (int mt = 0; mt < 2; mt++) {
#pragma unroll
        for (int kt = 0; kt < 8; kt++) {
            uint32_t lo4[4];
#pragma unroll
            for (int q = 0; q < 4; q++) {
                int rf = gid + (q & 1) * 8;
                int row;
                if (REORDER)
                    row = (rf >> 2) * 128 + w * 8 + mt * 4 + (rf & 3);
                else
                    row = w * 32 + mt * 16 + rf;
                int col = kt * 16 + qid * 2 + (q >> 1) * 8;
                float w0 = W[row * 128 + col];
                float w1 = W[row * 128 + col + 1];
                float h0 = bf16_rn(w0), h1 = bf16_rn(w1);
                wa[mt][kt][q] = pack_bf16x2(h0, h1);
                lo4[q] = pack_bf16x2(w0 - h0, w1 - h1);
            }
            *(uint4*)(alo + (((w * 2 + mt) * 8 + kt) * 32 + l) * 16) =
                make_uint4(lo4[0], lo4[1], lo4[2], lo4[3]);
        }
    }
}

// =====================================================================
// Layer-0 precompute (K=32, fp32 FFMA path)
// =====================================================================
template<int K>
__global__ __launch_bounds__(512, 1)
void precompute_kernel(const float* __restrict__ xext,
                       const float* __restrict__ Wih,
                       const float* __restrict__ bih,
                       const float* __restrict__ bhh)
{
    extern __shared__ float sm[];
    constexpr int CHUNKS = 8 * K / 4;
    float* xt = sm;                              // [2][8][K]

    const int j = threadIdx.x;
    const float* in = xext;

    ull wregp[K / 2];
#pragma unroll
    for (int kk = 0; kk < K / 2; kk++)
        wregp[kk] = pack2(Wih[j * K + 2 * kk], Wih[j * K + 2 * kk + 1]);
    const float bsum = bih[j] + bhh[j];

    const unsigned xt_s = smem_u32(xt);
    const int NT = TSEQ * (NB / 8);
    const int stride = gridDim.x;

    int tile0 = blockIdx.x;
    if (tile0 < NT && j < CHUNKS) {
        int t  = tile0 >> 6;
        int b0 = (tile0 & 63) << 3;
        int r  = j / (K / 4), kk = j % (K / 4);
        cpasync16(xt_s + (unsigned)(r * K + kk * 4) * 4,
                  &in[((size_t)(b0 + r) * TSEQ + t) * K + kk * 4]);
    }
    cpasync_commit();

    int buf = 0;
    for (int tile = blockIdx.x; tile < NT; tile += stride) {
        cpasync_wait0();
        __syncthreads();

        int nxt = tile + stride;
        if (nxt < NT && j < CHUNKS) {
            int tn  = nxt >> 6;
            int bn0 = (nxt & 63) << 3;
            int r   = j / (K / 4), kk = j % (K / 4);
            cpasync16(xt_s + (unsigned)((buf ^ 1) * 8 * K + r * K + kk * 4) * 4,
                      &in[((size_t)(bn0 + r) * TSEQ + tn) * K + kk * 4]);
        }
        cpasync_commit();

        const float* xtb = xt + buf * 8 * K;
        const int t  = tile >> 6;
        const int b0 = (tile & 63) << 3;

        ull acc[8] = {0, 0, 0, 0, 0, 0, 0, 0};
#pragma unroll
        for (int kq = 0; kq < K / 4; kq++) {
            ull w0 = wregp[2 * kq], w1 = wregp[2 * kq + 1];
#pragma unroll
            for (int r = 0; r < 8; r++) {
                ulonglong2 xv = *(const ulonglong2*)&xtb[r * K + 4 * kq];
                fma2(acc[r], xv.x, w0);
                fma2(acc[r], xv.y, w1);
            }
        }
        float v[8];
#pragma unroll
        for (int r = 0; r < 8; r++) {
            float2 f = unpack2(acc[r]);
            v[r] = bsum + f.x + f.y;
        }
        float* d1 = &g_xg[(((size_t)t * 128 + (b0 >> 2)) * 512 + j) * 4];
        *(float4*)d1          = make_float4(v[0], v[1], v[2], v[3]);
        *(float4*)(d1 + 2048) = make_float4(v[4], v[5], v[6], v[7]);
        buf ^= 1;
    }
}

// =====================================================================
// MMA precompute v3 (layers 1-3): 16 batch cols per alo pass
// (4 B-fragments), direct coalesced g_xg stores, double-buffered B
// stage -> ONE barrier per tile.  (R12 proven form)
// =====================================================================
__global__ __launch_bounds__(512, 1)
void precompute_mma_kernel(const float* __restrict__ Wih, int insel,
                           const float* __restrict__ bih,
                           const float* __restrict__ bhh)
{
    extern __shared__ char smraw[];
    char*     alo    = smraw;
    uint32_t* bstage = (uint32_t*)(smraw + PRE_BST_OFF);   // [2 buf][4 frag][512]

    const int j = threadIdx.x, w = j >> 5, l = j & 31;
    const int gid = l >> 2, qid = l & 3;
    const float* in = insel ? g_bufB : g_bufA;

    uint32_t wa[2][8][4];
    convert_weights<false>(Wih, alo, w, gid, qid, l, wa);

    float bs[2][2];
#pragma unroll
    for (int mt = 0; mt < 2; mt++) {
        int g0 = w * 32 + mt * 16 + gid;
        bs[mt][0] = bih[g0] + bhh[g0];
        bs[mt][1] = bih[g0 + 8] + bhh[g0 + 8];
    }

    const int ck = j & 127;
    const int cfr = j >> 7;
    uint32_t choff[4];
#pragma unroll
    for (int ci = 0; ci < 4; ci++) {
        uint32_t word = (ck >> 4) * 64 + ((ci * 4 + ((ck & 7) >> 1)) << 1)
                      + ((ck >> 3) & 1);
        choff[ci] = cfr * 2048 + word * 4 + (ck & 1) * 2;
    }

    const int NT = TSEQ * (NB / 16);
    const int stride = gridDim.x;

    {
        int t = blockIdx.x >> 5, b0 = (blockIdx.x & 31) * 16;
#pragma unroll
        for (int ci = 0; ci < 4; ci++) {
            float xv = in[((size_t)(b0 + cfr * 4 + ci) * TSEQ + t) * HID + ck];
            float hh = bf16_rn(xv);
            *(__nv_bfloat16*)((char*)bstage + choff[ci]) = __float2bfloat16(hh);
            *(__nv_bfloat16*)((char*)bstage + choff[ci] + 128) =
                __float2bfloat16(xv - hh);
        }
    }
    __syncthreads();

    int buf = 0;
    for (int tile = blockIdx.x; tile < NT; tile += stride) {
        const int t   = tile >> 5;
        const int bg0 = (tile & 31) * 4;

        float d[2][4][4];   // [mt][frag][q]
#pragma unroll
        for (int mt = 0; mt < 2; mt++)
#pragma unroll
            for (int f = 0; f < 4; f++) {
                if (qid < 2) {
                    d[mt][f][0] = bs[mt][0]; d[mt][f][1] = bs[mt][0];
                    d[mt][f][2] = bs[mt][1]; d[mt][f][3] = bs[mt][1];
                } else {
                    d[mt][f][0] = d[mt][f][1] = d[mt][f][2] = d[mt][f][3] = 0.f;
                }
            }

        int nxt = tile + stride;
        float xnext[4] = {0.f, 0.f, 0.f, 0.f};
        if (nxt < NT) {
            int tn = nxt >> 5, bn = (nxt & 31) * 16;
#pragma unroll
            for (int ci = 0; ci < 4; ci++)
                xnext[ci] = in[((size_t)(bn + cfr * 4 + ci) * TSEQ + tn) * HID + ck];
        }

        const uint32_t* bcur = bstage + buf * 2048;
#pragma unroll
        for (int kt = 0; kt < 8; kt++) {
            uint32_t bf[4][2];
#pragma unroll
            for (int f = 0; f < 4; f++) {
                uint2 v = *(const uint2*)&bcur[f * 512 + kt * 64 + 2 * l];
                bf[f][0] = v.x; bf[f][1] = v.y;
            }
            uint4 av0 = *(const uint4*)(alo + (((w * 2 + 0) * 8 + kt) * 32 + l) * 16);
            uint4 av1 = *(const uint4*)(alo + (((w * 2 + 1) * 8 + kt) * 32 + l) * 16);
#pragma unroll
            for (int f = 0; f < 4; f++) {
                mma16816(d[0][f], wa[0][kt], bf[f]);
                mma16816(d[1][f], wa[1][kt], bf[f]);
                mma16816(d[0][f], (const uint32_t*)&av0, bf[f]);
                mma16816(d[1][f], (const uint32_t*)&av1, bf[f]);
            }
        }

#pragma unroll
        for (int mt = 0; mt < 2; mt++)
#pragma unroll
            for (int f = 0; f < 4; f++)
#pragma unroll
                for (int q = 0; q < 4; q++)
                    d[mt][f][q] += __shfl_xor_sync(0xffffffffu, d[mt][f][q], 2);

        if (qid < 2) {
            int b = qid * 2;
#pragma unroll
            for (int mt = 0; mt < 2; mt++) {
                int g0 = w * 32 + mt * 16 + gid;
#pragma unroll
                for (int f = 0; f < 4; f++) {
                    float* dst = &g_xg[(((size_t)t * 128 + bg0 + f) * 512 + g0) * 4 + b];
                    *(float2*)dst        = make_float2(d[mt][f][0], d[mt][f][1]);
                    *(float2*)(dst + 32) = make_float2(d[mt][f][2], d[mt][f][3]);
                }
            }
        }

        {
            char* bnx = (char*)bstage + (buf ^ 1) * 8192;
#pragma unroll
            for (int ci = 0; ci < 4; ci++) {
                float nh = bf16_rn(xnext[ci]);
                *(__nv_bfloat16*)(bnx + choff[ci]) = __float2bfloat16(nh);
                *(__nv_bfloat16*)(bnx + choff[ci] + 128) =
                    __float2bfloat16(xnext[ci] - nh);
            }
        }
        __syncthreads();
        buf ^= 1;
    }
}

// =====================================================================
// MMA recurrent (R12 form + MUFU.TANH activations + optional out skip):
// 512 threads, split chains, full-warp tail, one barrier per step.
// outsel: 0 -> g_bufA, 1 -> g_bufB, -1 -> no out store (final layer).
// =====================================================================
__global__ __launch_bounds__(512, 1)
void recurrent_kernel(const float* __restrict__ Whh, int outsel, int layer)
{
    extern __shared__ char smraw[];
    char*     alo    = smraw;
    uint32_t* bstage = (uint32_t*)(smraw + REC_BST_OFF);   // [2][512] words

    const int j = threadIdx.x, w = j >> 5, l = j & 31;
    const int gid = l >> 2, qid = l & 3;
    const int bgrp = blockIdx.x;
    const int b0 = bgrp * 4;
    const bool wout = (outsel >= 0);
    float* out = (outsel == 1) ? g_bufB : g_bufA;

    uint32_t wa[2][8][4];
    convert_weights<true>(Whh, alo, w, gid, qid, l, wa);

    bstage[j] = 0;
    bstage[j + 512] = 0;

    // per-thread cell role (post-pairing)
    const int mts = qid >> 1;
    const int qd  = qid & 1;
    const int ulo = gid & 3;
    const int cbs = 2 * qd + (gid >> 2);
    const int us  = w * 8 + mts * 4 + ulo;
    float c = 0.f;

    const int glo0 = (gid >> 2) * 128 + w * 8 + 0 * 4 + ulo;
    const int glo1 = glo0 + 4;

    uint32_t bsh, bsl_;
    {
        uint32_t word = (us >> 4) * 64 + ((cbs * 4 + ((us & 7) >> 1)) << 1)
                      + ((us >> 3) & 1);
        bsh  = word * 4 + (us & 1) * 2;
        bsl_ = bsh + 128;
    }

    float2 xq[2][2];
    if (qid < 2) {
        const float* p0 = &g_xg[((size_t)0 + bgrp) * 2048 + glo0 * 4 + 2 * qid];
        xq[0][0] = *(const float2*)p0;
        xq[0][1] = *(const float2*)(p0 + 1024);
        const float* p1 = &g_xg[((size_t)0 + bgrp) * 2048 + glo1 * 4 + 2 * qid];
        xq[1][0] = *(const float2*)p1;
        xq[1][1] = *(const float2*)(p1 + 1024);
    }
    __syncthreads();

    for (int t = 0; t < TSEQ; t++) {
        float dh[2][4], dl[2][4];
#pragma unroll
        for (int mt = 0; mt < 2; mt++) {
            if (qid < 2) {
                dh[mt][0] = xq[mt][0].x; dh[mt][1] = xq[mt][0].y;
                dh[mt][2] = xq[mt][1].x; dh[mt][3] = xq[mt][1].y;
            } else {
                dh[mt][0] = dh[mt][1] = dh[mt][2] = dh[mt][3] = 0.f;
            }
            dl[mt][0] = dl[mt][1] = dl[mt][2] = dl[mt][3] = 0.f;
        }

        {
            int tn = (t + 1 < TSEQ) ? (t + 1) : t;
            if (qid < 2) {
                const float* p0 = &g_xg[((size_t)tn * 128 + bgrp) * 2048 + glo0 * 4 + 2 * qid];
                xq[0][0] = *(const float2*)p0;
                xq[0][1] = *(const float2*)(p0 + 1024);
                const float* p1 = &g_xg[((size_t)tn * 128 + bgrp) * 2048 + glo1 * 4 + 2 * qid];
                xq[1][0] = *(const float2*)p1;
                xq[1][1] = *(const float2*)(p1 + 1024);
            }
        }

        const uint32_t* bcur = bstage + (t & 1) * 512;
#pragma unroll
        for (int kt = 0; kt < 8; kt++) {
            uint2 bv = *(const uint2*)&bcur[kt * 64 + 2 * l];
            uint32_t bfr[2] = {bv.x, bv.y};
            uint4 av0 = *(const uint4*)(alo + (((w * 2 + 0) * 8 + kt) * 32 + l) * 16);
            uint4 av1 = *(const uint4*)(alo + (((w * 2 + 1) * 8 + kt) * 32 + l) * 16);
            mma16816(dh[0], wa[0][kt], bfr);
            mma16816(dh[1], wa[1][kt], bfr);
            mma16816(dl[0], (const uint32_t*)&av0, bfr);
            mma16816(dl[1], (const uint32_t*)&av1, bfr);
        }

        float dd[4], ee[4];
#pragma unroll
        for (int q = 0; q < 4; q++) {
            float d0 = dh[0][q] + dl[0][q];
            float d1 = dh[1][q] + dl[1][q];
            float own  = mts ? d1 : d0;
            float send = mts ? d0 : d1;
            dd[q] = own + __shfl_xor_sync(0xffffffffu, send, 2);
        }
#pragma unroll
        for (int q = 0; q < 4; q++)
            ee[q] = __shfl_xor_sync(0xffffffffu, dd[q], 16);

        {
            float pi, pf, pg, po;
            if (gid < 4) { pi = dd[0]; pf = ee[0]; pg = dd[2]; po = ee[2]; }
            else         { pi = ee[1]; pf = dd[1]; pg = ee[3]; po = dd[3]; }
            float iv = sig_fast(pi), fv = sig_fast(pf);
            float gv = tanh_fast(pg), ov = sig_fast(po);
            c = fv * c + iv * gv;
            float h = ov * tanh_fast(c);
            if (wout)
                out[((size_t)(b0 + cbs) * TSEQ + t) * HID + us] = h;
            if (t == TSEQ - 1)
                g_hN[layer * (NB * HID) + (b0 + cbs) * HID + us] = h;
            float hh = bf16_rn(h);
            char* bnx = (char*)bstage + ((t + 1) & 1) * 2048;
            *(__nv_bfloat16*)(bnx + bsh)  = __float2bfloat16(hh);
            *(__nv_bfloat16*)(bnx + bsl_) = __float2bfloat16(h - hh);
        }
        __syncthreads();   // h(t) published for step t+1
    }
}

// =====================================================================
// Heads: hN [4,512,128] -> (opt, tp, sl, lot), each [4,512,4]
// =====================================================================
__global__ void heads_kernel(
    const float* __restrict__ Wopt, const float* __restrict__ bopt,
    const float* __restrict__ Wlot, const float* __restrict__ blot,
    const float* __restrict__ Wtp,  const float* __restrict__ btp,
    const float* __restrict__ Wsl,  const float* __restrict__ bsl,
    float* __restrict__ outp)
{
    int tid = blockIdx.x * blockDim.x + threadIdx.x;
    if (tid >= 4 * 2048) return;
    int head = tid >> 11;
    int r    = tid & 2047;
    const float* W; const float* b;
    if      (head == 0) { W = Wopt; b = bopt; }
    else if (head == 1) { W = Wtp;  b = btp;  }
    else if (head == 2) { W = Wsl;  b = bsl;  }
    else                { W = Wlot; b = blot; }

    float y0 = b[0], y1 = b[1], y2 = b[2], y3 = b[3];
    const float4* hv = (const float4*)&g_hN[r * HID];
    const float4* w0 = (const float4*)&W[0];
    const float4* w1 = (const float4*)&W[128];
    const float4* w2 = (const float4*)&W[256];
    const float4* w3 = (const float4*)&W[384];
#pragma unroll 8
    for (int q = 0; q < 32; q++) {
        float4 h = hv[q];
        float4 a  = w0[q]; y0 += h.x*a.x  + h.y*a.y  + h.z*a.z  + h.w*a.w;
        float4 bq = w1[q]; y1 += h.x*bq.x + h.y*bq.y + h.z*bq.z + h.w*bq.w;
        float4 cq = w2[q]; y2 += h.x*cq.x + h.y*cq.y + h.z*cq.z + h.w*cq.w;
        float4 dq = w3[q]; y3 += h.x*dq.x + h.y*dq.y + h.z*dq.z + h.w*dq.w;
    }
    float o0, o1, o2, o3;
    if (head == 0) {
        float m = fmaxf(fmaxf(y0, y1), fmaxf(y2, y3));
        float e0 = __expf(y0 - m), e1 = __expf(y1 - m),
              e2 = __expf(y2 - m), e3 = __expf(y3 - m);
        float s = e0 + e1 + e2 + e3;
        float p0 = e0 / s, p1 = e1 / s, p2 = e2 / s, p3 = e3 / s;
        m = fmaxf(fmaxf(p0, p1), fmaxf(p2, p3));
        e0 = __expf(p0 - m); e1 = __expf(p1 - m);
        e2 = __expf(p2 - m); e3 = __expf(p3 - m);
        s = e0 + e1 + e2 + e3;
        o0 = e0 / s; o1 = e1 / s; o2 = e2 / s; o3 = e3 / s;
    } else {
        o0 = sigx(sigx(y0)); o1 = sigx(sigx(y1));
        o2 = sigx(sigx(y2)); o3 = sigx(sigx(y3));
    }
    float* dst = outp + head * 8192 + r * 4;
    dst[0] = o0; dst[1] = o1; dst[2] = o2; dst[3] = o3;
}

// =====================================================================
extern "C" void kernel_launch(void* const* d_in, const int* in_sizes, int n_in,
                              void* d_out, int out_size)
{
    const float* x      = (const float*)d_in[0];
    const float* Wih0   = (const float*)d_in[1];
    const float* Whh0   = (const float*)d_in[2];
    const float* bih0   = (const float*)d_in[3];
    const float* bhh0   = (const float*)d_in[4];
    const float* Wih123 = (const float*)d_in[5];
    const float* Whh123 = (const float*)d_in[6];
    const float* bih123 = (const float*)d_in[7];
    const float* bhh123 = (const float*)d_in[8];
    const float* Wopt   = (const float*)d_in[9];
    const float* bopt   = (const float*)d_in[10];
    const float* Wlot   = (const float*)d_in[11];
    const float* blot   = (const float*)d_in[12];
    const float* Wtp    = (const float*)d_in[13];
    const float* btp    = (const float*)d_in[14];
    const float* Wsl    = (const float*)d_in[15];
    const float* bsl    = (const float*)d_in[16];
    float* outp = (float*)d_out;

    const int SM_PRE32 = 2 * 8 * 32 * 4;   // 2048

    cudaFuncSetAttribute(recurrent_kernel,
                         cudaFuncAttributeMaxDynamicSharedMemorySize, REC_SMEM);
    cudaFuncSetAttribute(precompute_mma_kernel,
                         cudaFuncAttributeMaxDynamicSharedMemorySize, PRE_SMEM);

    // layer 0
    precompute_kernel<32><<<148, 512, SM_PRE32>>>(x, Wih0, bih0, bhh0);
    recurrent_kernel<<<128, 512, REC_SMEM>>>(Whh0, /*out=A*/0, /*layer*/0);
    // layer 1 (in A -> out B)
    precompute_mma_kernel<<<148, 512, PRE_SMEM>>>(Wih123 + 0 * G4 * HID, 0,
        bih123 + 0 * G4, bhh123 + 0 * G4);
    recurrent_kernel<<<128, 512, REC_SMEM>>>(Whh123 + 0 * G4 * HID, 1, 1);
    // layer 2 (in B -> out A)
    precompute_mma_kernel<<<148, 512, PRE_SMEM>>>(Wih123 + 1 * G4 * HID, 1,
        bih123 + 1 * G4, bhh123 + 1 * G4);
    recurrent_kernel<<<128, 512, REC_SMEM>>>(Whh123 + 1 * G4 * HID, 0, 2);
    // layer 3 (in A -> final, no out buffer needed)
    precompute_mma_kernel<<<148, 512, PRE_SMEM>>>(Wih123 + 2 * G4 * HID, 0,
        bih123 + 2 * G4, bhh123 + 2 * G4);
    recurrent_kernel<<<128, 512, REC_SMEM>>>(Whh123 + 2 * G4 * HID, -1, 3);
    // heads
    heads_kernel<<<(4 * 2048 + 255) / 256, 256>>>(
        Wopt, bopt, Wlot, blot, Wtp, btp, Wsl, bsl, outp);
}